// round 1
// baseline (speedup 1.0000x reference)
#include <cuda_runtime.h>
#include <math.h>

#define Bsz    16
#define Sd     4096
#define Hd     2048
#define POOLD  4096
#define SPLITS 64
#define ROWS   (Sd / SPLITS)          // 64 rows per main-pass block
#define SCALE  0.022097086912079608f  // 1/sqrt(2048)
#define EPSV   1e-6f

// ---------------- scratch (no allocations allowed) ----------------
__device__ float g_q[Hd];
__device__ float g_qk[Hd];
__device__ float g_pm[Bsz * SPLITS];
__device__ float g_pl[Bsz * SPLITS];
__device__ float g_pacc[Bsz * SPLITS * Hd];   // 8.4 MB
__device__ float g_xp[Bsz * Hd];
__device__ float g_pooled[Bsz * Hd];
__device__ float g_normed[Bsz * Hd];

// ---------------- 1. zero init (atomic targets) ----------------
__global__ void zero_kernel(float* __restrict__ out) {
    int i = blockIdx.x * 256 + threadIdx.x;   // grid covers 65536
    if (i < Hd)        g_qk[i] = 0.f;
    if (i < Bsz * Hd)  g_pooled[i] = 0.f;
    out[i] = 0.f;
}

// ---------------- 2. q[d] = dot(Wq[d,:], lq) ----------------
__global__ void qproj_kernel(const float* __restrict__ Wq,
                             const float* __restrict__ lq) {
    int d    = blockIdx.x * 8 + (threadIdx.x >> 5);
    int lane = threadIdx.x & 31;
    const float4* r4 = (const float4*)(Wq + (size_t)d * Hd);
    const float4* v4 = (const float4*)lq;
    float s = 0.f;
#pragma unroll
    for (int i = 0; i < 16; i++) {
        float4 a = r4[lane + 32 * i];
        float4 b = v4[lane + 32 * i];
        s += a.x * b.x + a.y * b.y + a.z * b.z + a.w * b.w;
    }
#pragma unroll
    for (int o = 16; o; o >>= 1) s += __shfl_xor_sync(0xffffffffu, s, o);
    if (lane == 0) g_q[d] = s;
}

// ---------------- 3. qk[h] = sum_d Wk[d,h] * q[d] ----------------
__global__ void kproj_kernel(const float* __restrict__ Wk) {
    int h  = blockIdx.x * 256 + threadIdx.x;
    int d0 = blockIdx.y * 64;
    float a = 0.f;
#pragma unroll 8
    for (int d = 0; d < 64; d++)
        a += Wk[(size_t)(d0 + d) * Hd + h] * g_q[d0 + d];
    atomicAdd(&g_qk[h], a);
}

// ---------------- 4. main flash pass over X ----------------
// block = (split sp, batch b); 256 threads; 8 floats of H per thread.
__global__ void main_pass(const float* __restrict__ X,
                          const int* __restrict__ mask) {
    __shared__ float red[16];   // 8 warps x 2 parity buffers
    __shared__ float bro[2];
    int b = blockIdx.y, sp = blockIdx.x;
    int t = threadIdx.x, lane = t & 31, warp = t >> 5;

    const float4* qk4 = (const float4*)g_qk;
    float4 qa = qk4[t];
    float4 qb = qk4[t + 256];

    float m = -INFINITY, l = 0.f;
    float4 a0 = make_float4(0.f, 0.f, 0.f, 0.f);
    float4 a1 = make_float4(0.f, 0.f, 0.f, 0.f);

    const float4* X4 = (const float4*)(X + ((size_t)b * Sd + (size_t)sp * ROWS) * Hd);
    const int* mk = mask + (size_t)b * Sd + (size_t)sp * ROWS;

    for (int r = 0; r < ROWS; r++) {
        if (mk[r] == 0) continue;          // masked row: exact zero weight, skip read
        float4 xa = X4[(size_t)r * 512 + t];
        float4 xb = X4[(size_t)r * 512 + 256 + t];
        float p = xa.x * qa.x + xa.y * qa.y + xa.z * qa.z + xa.w * qa.w
                + xb.x * qb.x + xb.y * qb.y + xb.z * qb.z + xb.w * qb.w;
#pragma unroll
        for (int o = 16; o; o >>= 1) p += __shfl_xor_sync(0xffffffffu, p, o);
        int pb = r & 1;
        if (lane == 0) red[pb * 8 + warp] = p;
        __syncthreads();
        if (t == 0) {
            float s = 0.f;
#pragma unroll
            for (int w = 0; w < 8; w++) s += red[pb * 8 + w];
            bro[pb] = s;
        }
        __syncthreads();
        float score = bro[pb] * SCALE;

        float mn = fmaxf(m, score);
        float c  = __expf(m - mn);        // 0 when m == -inf
        float p2 = __expf(score - mn);
        l = l * c + p2;
        a0.x = a0.x * c + p2 * xa.x;  a0.y = a0.y * c + p2 * xa.y;
        a0.z = a0.z * c + p2 * xa.z;  a0.w = a0.w * c + p2 * xa.w;
        a1.x = a1.x * c + p2 * xb.x;  a1.y = a1.y * c + p2 * xb.y;
        a1.z = a1.z * c + p2 * xb.z;  a1.w = a1.w * c + p2 * xb.w;
        m = mn;
    }

    if (t == 0) {
        g_pm[b * SPLITS + sp] = m;
        g_pl[b * SPLITS + sp] = l;
    }
    float4* pa = (float4*)(g_pacc + (size_t)(b * SPLITS + sp) * Hd);
    pa[t] = a0;
    pa[t + 256] = a1;
}

// ---------------- 5. combine partials -> xp[b,:] ----------------
__global__ void combine_kernel() {
    __shared__ float ex[SPLITS];
    __shared__ float sm[2];
    int b = blockIdx.x, t = threadIdx.x;

    if (t == 0) {
        float M = -INFINITY;
        for (int i = 0; i < SPLITS; i++) M = fmaxf(M, g_pm[b * SPLITS + i]);
        sm[0] = M;
    }
    __syncthreads();
    float M = sm[0];
    if (t < SPLITS) ex[t] = __expf(g_pm[b * SPLITS + t] - M);
    __syncthreads();
    if (t == 0) {
        float lt = 0.f;
        for (int i = 0; i < SPLITS; i++) lt += g_pl[b * SPLITS + i] * ex[i];
        sm[1] = lt;
    }
    __syncthreads();
    float inv = 1.f / sm[1];

    float4 s0 = make_float4(0.f, 0.f, 0.f, 0.f);
    float4 s1 = make_float4(0.f, 0.f, 0.f, 0.f);
    for (int i = 0; i < SPLITS; i++) {
        const float4* pa = (const float4*)(g_pacc + (size_t)(b * SPLITS + i) * Hd);
        float e = ex[i];
        float4 v = pa[t];
        s0.x += e * v.x; s0.y += e * v.y; s0.z += e * v.z; s0.w += e * v.w;
        v = pa[t + 256];
        s1.x += e * v.x; s1.y += e * v.y; s1.z += e * v.z; s1.w += e * v.w;
    }
    float4* xp4 = (float4*)(g_xp + (size_t)b * Hd);
    s0.x *= inv; s0.y *= inv; s0.z *= inv; s0.w *= inv;
    s1.x *= inv; s1.y *= inv; s1.z *= inv; s1.w *= inv;
    xp4[t] = s0;
    xp4[t + 256] = s1;
}

// ---------------- 6./8. skinny GEMM: out[b,d] += sum_k W[d,k]*xin[b,k] ----------------
// grid = (D/64, ksplits); 128 threads; thread tile 4d x 2b; split-K via atomics.
__global__ void skinny_gemm(const float* __restrict__ W, int mode,
                            float* __restrict__ dout, int D, int K) {
    __shared__ float ws[64][65];
    __shared__ float xs[16][65];
    const float* xin = (mode == 0) ? g_xp : g_normed;
    float* out       = (mode == 0) ? g_pooled : dout;

    int t  = threadIdx.x;
    int d0 = blockIdx.x * 64;
    int kchunk = K / gridDim.y;
    int k0 = blockIdx.y * kchunk;
    int b0 = (t & 7) * 2;
    int dg = t >> 3;

    float acc[4][2] = {{0.f,0.f},{0.f,0.f},{0.f,0.f},{0.f,0.f}};

    for (int kc = k0; kc < k0 + kchunk; kc += 64) {
        for (int i = t; i < 1024; i += 128) {
            int row = i >> 4, c4 = i & 15;
            float4 v = *(const float4*)&W[(size_t)(d0 + row) * K + kc + c4 * 4];
            ws[row][c4 * 4 + 0] = v.x; ws[row][c4 * 4 + 1] = v.y;
            ws[row][c4 * 4 + 2] = v.z; ws[row][c4 * 4 + 3] = v.w;
        }
        for (int i = t; i < 256; i += 128) {
            int row = i >> 4, c4 = i & 15;
            float4 v = *(const float4*)&xin[(size_t)row * K + kc + c4 * 4];
            xs[row][c4 * 4 + 0] = v.x; xs[row][c4 * 4 + 1] = v.y;
            xs[row][c4 * 4 + 2] = v.z; xs[row][c4 * 4 + 3] = v.w;
        }
        __syncthreads();
#pragma unroll 8
        for (int kt = 0; kt < 64; kt++) {
            float x0 = xs[b0][kt], x1 = xs[b0 + 1][kt];
#pragma unroll
            for (int r = 0; r < 4; r++) {
                float w = ws[dg * 4 + r][kt];
                acc[r][0] += w * x0;
                acc[r][1] += w * x1;
            }
        }
        __syncthreads();
    }
#pragma unroll
    for (int r = 0; r < 4; r++) {
        atomicAdd(&out[(size_t)(b0 + 0) * D + d0 + dg * 4 + r], acc[r][0]);
        atomicAdd(&out[(size_t)(b0 + 1) * D + d0 + dg * 4 + r], acc[r][1]);
    }
}

// ---------------- 7. rmsnorm ----------------
__global__ void rmsnorm_kernel(const float* __restrict__ nw) {
    __shared__ float red[8];
    __shared__ float sv;
    int b = blockIdx.x, t = threadIdx.x, lane = t & 31, warp = t >> 5;
    const float4* p4 = (const float4*)(g_pooled + (size_t)b * Hd);
    float4 v0 = p4[t], v1 = p4[t + 256];
    float ss = v0.x*v0.x + v0.y*v0.y + v0.z*v0.z + v0.w*v0.w
             + v1.x*v1.x + v1.y*v1.y + v1.z*v1.z + v1.w*v1.w;
#pragma unroll
    for (int o = 16; o; o >>= 1) ss += __shfl_xor_sync(0xffffffffu, ss, o);
    if (lane == 0) red[warp] = ss;
    __syncthreads();
    if (t == 0) {
        float s = 0.f;
#pragma unroll
        for (int w = 0; w < 8; w++) s += red[w];
        sv = rsqrtf(s / (float)Hd + EPSV);
    }
    __syncthreads();
    float rs = sv;
    const float4* w4 = (const float4*)nw;
    float4* n4 = (float4*)(g_normed + (size_t)b * Hd);
    float4 wa = w4[t], wb = w4[t + 256];
    float4 o0, o1;
    o0.x = v0.x * rs * wa.x; o0.y = v0.y * rs * wa.y;
    o0.z = v0.z * rs * wa.z; o0.w = v0.w * rs * wa.w;
    o1.x = v1.x * rs * wb.x; o1.y = v1.y * rs * wb.y;
    o1.z = v1.z * rs * wb.z; o1.w = v1.w * rs * wb.w;
    n4[t] = o0;
    n4[t + 256] = o1;
}

// ---------------- launch ----------------
extern "C" void kernel_launch(void* const* d_in, const int* in_sizes, int n_in,
                              void* d_out, int out_size) {
    const float* X  = (const float*)d_in[0];
    const int*   mk = (const int*)d_in[1];
    const float* lq = (const float*)d_in[2];
    const float* Wq = (const float*)d_in[3];
    const float* Wk = (const float*)d_in[4];
    const float* Wv = (const float*)d_in[5];
    const float* Wo = (const float*)d_in[6];
    const float* nw = (const float*)d_in[7];
    float* out = (float*)d_out;

    zero_kernel<<<256, 256>>>(out);                          // 65536 threads
    qproj_kernel<<<Hd / 8, 256>>>(Wq, lq);                   // q = Wq @ lq
    kproj_kernel<<<dim3(Hd / 256, 32), 256>>>(Wk);           // qk = Wk^T q
    main_pass<<<dim3(SPLITS, Bsz), 256>>>(X, mk);            // online softmax over X
    combine_kernel<<<Bsz, 256>>>();                          // merge splits -> xp
    skinny_gemm<<<dim3(Hd / 64, 16), 128>>>(Wv, 0, out, Hd, Hd);      // pooled = xp @ Wv^T
    rmsnorm_kernel<<<Bsz, 256>>>(nw);                        // normed
    skinny_gemm<<<dim3(POOLD / 64, 8), 128>>>(Wo, 1, out, POOLD, Hd); // out = normed @ Wo^T
}

// round 2
// speedup vs baseline: 1.2045x; 1.2045x over previous
#include <cuda_runtime.h>
#include <math.h>

#define Bsz    16
#define Sd     4096
#define Hd     2048
#define POOLD  4096
#define SPLITS 64
#define ROWS   64                     // rows per main-pass block
#define RPW    16                     // rows per warp (4 warps/block)
#define SCALE  0.022097086912079608f  // 1/sqrt(2048)
#define EPSV   1e-6f

// ---------------- scratch ----------------
__device__ float g_q[Hd];
__device__ float g_qk[Hd];
__device__ float g_pm[Bsz * SPLITS];
__device__ float g_pl[Bsz * SPLITS];
__device__ float g_ew[Bsz * SPLITS];
__device__ float g_inv[Bsz];
__device__ float g_pacc[Bsz * SPLITS * Hd];   // 8.4 MB
__device__ float g_xp[Bsz * Hd];
__device__ float g_pooled[Bsz * Hd];
__device__ float g_normed[Bsz * Hd];

// ---------------- 1. zero init (atomic targets) ----------------
__global__ void zero_kernel(float* __restrict__ out) {
    int i = blockIdx.x * 256 + threadIdx.x;   // grid covers 65536
    if (i < Hd)        g_qk[i] = 0.f;
    if (i < Bsz * Hd)  g_pooled[i] = 0.f;
    out[i] = 0.f;
}

// ---------------- 2. q[d] = dot(Wq[d,:], lq) ----------------
__global__ void qproj_kernel(const float* __restrict__ Wq,
                             const float* __restrict__ lq) {
    int d    = blockIdx.x * 8 + (threadIdx.x >> 5);
    int lane = threadIdx.x & 31;
    const float4* r4 = (const float4*)(Wq + (size_t)d * Hd);
    const float4* v4 = (const float4*)lq;
    float s = 0.f;
#pragma unroll
    for (int i = 0; i < 16; i++) {
        float4 a = r4[lane + 32 * i];
        float4 b = v4[lane + 32 * i];
        s += a.x * b.x + a.y * b.y + a.z * b.z + a.w * b.w;
    }
#pragma unroll
    for (int o = 16; o; o >>= 1) s += __shfl_xor_sync(0xffffffffu, s, o);
    if (lane == 0) g_q[d] = s;
}

// ---------------- 3. qk[h] = sum_d Wk[d,h] * q[d] ----------------
__global__ void kproj_kernel(const float* __restrict__ Wk) {
    int h  = blockIdx.x * 256 + threadIdx.x;
    int d0 = blockIdx.y * 64;
    float a = 0.f;
#pragma unroll 8
    for (int d = 0; d < 64; d++)
        a += Wk[(size_t)(d0 + d) * Hd + h] * g_q[d0 + d];
    atomicAdd(&g_qk[h], a);
}

// ---------------- 4. main flash pass over X (warp-per-row) ----------------
// grid = (SPLITS, Bsz), 128 threads (4 warps), each warp 16 rows.
// Lane holds H elements at float4 indices lane + 32*i, i in [0,16).
__global__ void __launch_bounds__(128, 3)
main_pass(const float* __restrict__ X, const int* __restrict__ mask) {
    __shared__ float4 sbuf[4][512];   // sbuf[0] holds qk during loop; all 4 are merge buffers after
    __shared__ float s_m[4], s_l[4];
    int b = blockIdx.y, sp = blockIdx.x;
    int t = threadIdx.x, lane = t & 31, warp = t >> 5;

    const float4* qk4 = (const float4*)g_qk;
    for (int i = t; i < 512; i += 128) sbuf[0][i] = qk4[i];
    __syncthreads();

    float m = -INFINITY, l = 0.f;
    float4 acc[16];
#pragma unroll
    for (int i = 0; i < 16; i++) acc[i] = make_float4(0.f, 0.f, 0.f, 0.f);

    const float4* X4 = (const float4*)(X + ((size_t)b * Sd + (size_t)sp * ROWS + warp * RPW) * Hd);
    const int* mk = mask + (size_t)b * Sd + sp * ROWS + warp * RPW;

    for (int r = 0; r < RPW; r++) {
        if (mk[r] == 0) continue;          // masked row: weight exactly 0, skip the read
        float4 x[16];
#pragma unroll
        for (int i = 0; i < 16; i++) x[i] = X4[(size_t)r * 512 + lane + 32 * i];
        float p = 0.f;
#pragma unroll
        for (int i = 0; i < 16; i++) {
            float4 qv = sbuf[0][lane + 32 * i];
            p += x[i].x * qv.x + x[i].y * qv.y + x[i].z * qv.z + x[i].w * qv.w;
        }
#pragma unroll
        for (int o = 16; o; o >>= 1) p += __shfl_xor_sync(0xffffffffu, p, o);
        float score = p * SCALE;
        if (score > m) {                   // rare after the first few rows
            float c = __expf(m - score);   // exact 0 on first active row
            l *= c;
#pragma unroll
            for (int i = 0; i < 16; i++) {
                acc[i].x *= c; acc[i].y *= c; acc[i].z *= c; acc[i].w *= c;
            }
            m = score;
        }
        float p2 = __expf(score - m);
        l += p2;
#pragma unroll
        for (int i = 0; i < 16; i++) {
            acc[i].x += p2 * x[i].x; acc[i].y += p2 * x[i].y;
            acc[i].z += p2 * x[i].z; acc[i].w += p2 * x[i].w;
        }
    }

    if (lane == 0) { s_m[warp] = m; s_l[warp] = l; }
    __syncthreads();                       // also: everyone done reading qk from sbuf[0]
    float M = fmaxf(fmaxf(s_m[0], s_m[1]), fmaxf(s_m[2], s_m[3]));
    float e = (m == -INFINITY) ? 0.f : __expf(m - M);
#pragma unroll
    for (int i = 0; i < 16; i++) {
        float4 v = acc[i];
        v.x *= e; v.y *= e; v.z *= e; v.w *= e;
        sbuf[warp][lane + 32 * i] = v;
    }
    __syncthreads();
    if (t == 0) {
        float lt = 0.f;
#pragma unroll
        for (int w = 0; w < 4; w++)
            lt += (s_m[w] == -INFINITY) ? 0.f : s_l[w] * __expf(s_m[w] - M);
        g_pm[b * SPLITS + sp] = M;
        g_pl[b * SPLITS + sp] = lt;
    }
    float4* pa = (float4*)(g_pacc + (size_t)(b * SPLITS + sp) * Hd);
    for (int i = t; i < 512; i += 128) {
        float4 a = sbuf[0][i], v1 = sbuf[1][i], v2 = sbuf[2][i], v3 = sbuf[3][i];
        a.x += v1.x + v2.x + v3.x; a.y += v1.y + v2.y + v3.y;
        a.z += v1.z + v2.z + v3.z; a.w += v1.w + v2.w + v3.w;
        pa[i] = a;
    }
}

// ---------------- 5a. per-batch softmax stats ----------------
__global__ void softmax_stats() {          // grid = Bsz, 32 threads
    int b = blockIdx.x, lane = threadIdx.x;
    float m0 = g_pm[b * SPLITS + lane];
    float m1 = g_pm[b * SPLITS + 32 + lane];
    float M = fmaxf(m0, m1);
#pragma unroll
    for (int o = 16; o; o >>= 1) M = fmaxf(M, __shfl_xor_sync(0xffffffffu, M, o));
    float e0 = (m0 == -INFINITY) ? 0.f : __expf(m0 - M);
    float e1 = (m1 == -INFINITY) ? 0.f : __expf(m1 - M);
    float s = g_pl[b * SPLITS + lane] * e0 + g_pl[b * SPLITS + 32 + lane] * e1;
#pragma unroll
    for (int o = 16; o; o >>= 1) s += __shfl_xor_sync(0xffffffffu, s, o);
    g_ew[b * SPLITS + lane] = e0;
    g_ew[b * SPLITS + 32 + lane] = e1;
    if (lane == 0) g_inv[b] = 1.f / s;
}

// ---------------- 5b. combine partials -> xp ----------------
__global__ void combine_kernel() {         // grid = (Bsz, 8), 64 threads
    int b = blockIdx.x;
    int idx = blockIdx.y * 64 + threadIdx.x;   // float4 index in [0,512)
    float inv = g_inv[b];
    float4 s = make_float4(0.f, 0.f, 0.f, 0.f);
    const float4* pa = (const float4*)g_pacc;
#pragma unroll 4
    for (int i = 0; i < SPLITS; i++) {
        float e = g_ew[b * SPLITS + i];
        float4 v = pa[(size_t)(b * SPLITS + i) * 512 + idx];
        s.x += e * v.x; s.y += e * v.y; s.z += e * v.z; s.w += e * v.w;
    }
    s.x *= inv; s.y *= inv; s.z *= inv; s.w *= inv;
    ((float4*)(g_xp + (size_t)b * Hd))[idx] = s;
}

// ---------------- 6./8. skinny GEMM: out[b,d] += sum_k W[d,k]*xin[b,k] ----------------
__global__ void skinny_gemm(const float* __restrict__ W, int mode,
                            float* __restrict__ dout, int D, int K) {
    __shared__ float ws[64][65];
    __shared__ float xs[16][65];
    const float* xin = (mode == 0) ? g_xp : g_normed;
    float* out       = (mode == 0) ? g_pooled : dout;

    int t  = threadIdx.x;
    int d0 = blockIdx.x * 64;
    int kchunk = K / gridDim.y;
    int k0 = blockIdx.y * kchunk;
    int b0 = (t & 7) * 2;
    int dg = t >> 3;

    float acc[4][2] = {{0.f,0.f},{0.f,0.f},{0.f,0.f},{0.f,0.f}};

    for (int kc = k0; kc < k0 + kchunk; kc += 64) {
        for (int i = t; i < 1024; i += 128) {
            int row = i >> 4, c4 = i & 15;
            float4 v = *(const float4*)&W[(size_t)(d0 + row) * K + kc + c4 * 4];
            ws[row][c4 * 4 + 0] = v.x; ws[row][c4 * 4 + 1] = v.y;
            ws[row][c4 * 4 + 2] = v.z; ws[row][c4 * 4 + 3] = v.w;
        }
        for (int i = t; i < 256; i += 128) {
            int row = i >> 4, c4 = i & 15;
            float4 v = *(const float4*)&xin[(size_t)row * K + kc + c4 * 4];
            xs[row][c4 * 4 + 0] = v.x; xs[row][c4 * 4 + 1] = v.y;
            xs[row][c4 * 4 + 2] = v.z; xs[row][c4 * 4 + 3] = v.w;
        }
        __syncthreads();
#pragma unroll 8
        for (int kt = 0; kt < 64; kt++) {
            float x0 = xs[b0][kt], x1 = xs[b0 + 1][kt];
#pragma unroll
            for (int r = 0; r < 4; r++) {
                float w = ws[dg * 4 + r][kt];
                acc[r][0] += w * x0;
                acc[r][1] += w * x1;
            }
        }
        __syncthreads();
    }
#pragma unroll
    for (int r = 0; r < 4; r++) {
        atomicAdd(&out[(size_t)(b0 + 0) * D + d0 + dg * 4 + r], acc[r][0]);
        atomicAdd(&out[(size_t)(b0 + 1) * D + d0 + dg * 4 + r], acc[r][1]);
    }
}

// ---------------- 7. rmsnorm ----------------
__global__ void rmsnorm_kernel(const float* __restrict__ nw) {
    __shared__ float red[8];
    __shared__ float sv;
    int b = blockIdx.x, t = threadIdx.x, lane = t & 31, warp = t >> 5;
    const float4* p4 = (const float4*)(g_pooled + (size_t)b * Hd);
    float4 v0 = p4[t], v1 = p4[t + 256];
    float ss = v0.x*v0.x + v0.y*v0.y + v0.z*v0.z + v0.w*v0.w
             + v1.x*v1.x + v1.y*v1.y + v1.z*v1.z + v1.w*v1.w;
#pragma unroll
    for (int o = 16; o; o >>= 1) ss += __shfl_xor_sync(0xffffffffu, ss, o);
    if (lane == 0) red[warp] = ss;
    __syncthreads();
    if (t == 0) {
        float s = 0.f;
#pragma unroll
        for (int w = 0; w < 8; w++) s += red[w];
        sv = rsqrtf(s / (float)Hd + EPSV);
    }
    __syncthreads();
    float rs = sv;
    const float4* w4 = (const float4*)nw;
    float4* n4 = (float4*)(g_normed + (size_t)b * Hd);
    float4 wa = w4[t], wb = w4[t + 256];
    float4 o0, o1;
    o0.x = v0.x * rs * wa.x; o0.y = v0.y * rs * wa.y;
    o0.z = v0.z * rs * wa.z; o0.w = v0.w * rs * wa.w;
    o1.x = v1.x * rs * wb.x; o1.y = v1.y * rs * wb.y;
    o1.z = v1.z * rs * wb.z; o1.w = v1.w * rs * wb.w;
    n4[t] = o0;
    n4[t + 256] = o1;
}

// ---------------- launch ----------------
extern "C" void kernel_launch(void* const* d_in, const int* in_sizes, int n_in,
                              void* d_out, int out_size) {
    const float* X  = (const float*)d_in[0];
    const int*   mk = (const int*)d_in[1];
    const float* lq = (const float*)d_in[2];
    const float* Wq = (const float*)d_in[3];
    const float* Wk = (const float*)d_in[4];
    const float* Wv = (const float*)d_in[5];
    const float* Wo = (const float*)d_in[6];
    const float* nw = (const float*)d_in[7];
    float* out = (float*)d_out;

    zero_kernel<<<256, 256>>>(out);
    qproj_kernel<<<Hd / 8, 256>>>(Wq, lq);                   // q = Wq @ lq
    kproj_kernel<<<dim3(Hd / 256, 32), 256>>>(Wk);           // qk = Wk^T q
    main_pass<<<dim3(SPLITS, Bsz), 128>>>(X, mk);            // online softmax over X
    softmax_stats<<<Bsz, 32>>>();                            // per-batch M, 1/l, split weights
    combine_kernel<<<dim3(Bsz, 8), 64>>>();                  // merge splits -> xp
    skinny_gemm<<<dim3(Hd / 64, 16), 128>>>(Wv, 0, out, Hd, Hd);      // pooled = xp @ Wv^T
    rmsnorm_kernel<<<Bsz, 256>>>(nw);                        // normed
    skinny_gemm<<<dim3(POOLD / 64, 8), 128>>>(Wo, 1, out, POOLD, Hd); // out = normed @ Wo^T
}